// round 15
// baseline (speedup 1.0000x reference)
#include <cuda_runtime.h>
#include <cuda_fp16.h>
#include <cstdint>

#define N_VERTS 40962
#define N_POOL  10242

// h1 single fp16, layout [n][b][c] (c innermost, 512 halfs = 1KB per vertex)
__device__ __half g_h1[N_VERTS * 512];
__device__ __half g_h2[N_VERTS * 512];         // fp16 [n][b][c] (1KB per vertex)
__device__ float g_h3[128 * N_POOL * 8];       // [(o*N_POOL+n)*8+b]
__device__ int   g_nebs[N_VERTS * 7];
__device__ __half g_W2h[7 * 64 * 64];          // [k][o][c] fp16
__device__ __half g_W3h[128 * 64];             // [o][c] fp16

// ---------------- helpers ----------------
__device__ __forceinline__ uint32_t smem_u32(const void* p) {
    uint32_t a;
    asm("{ .reg .u64 t; cvta.to.shared.u64 t, %1; cvt.u32.u64 %0, t; }"
        : "=r"(a) : "l"(p));
    return a;
}
__device__ __forceinline__ uint32_t swz(uint32_t off) {
    return off ^ ((off >> 3) & 0x70u);
}
__device__ __forceinline__ void ldsm_x4(uint32_t* r, uint32_t addr) {
    asm volatile(
        "ldmatrix.sync.aligned.m8n8.x4.shared.b16 {%0,%1,%2,%3}, [%4];"
        : "=r"(r[0]), "=r"(r[1]), "=r"(r[2]), "=r"(r[3]) : "r"(addr));
}
__device__ __forceinline__ void mma_f16(float* d, const uint32_t* a,
                                        const uint32_t* b) {
    asm volatile(
        "mma.sync.aligned.m16n8k16.row.col.f32.f16.f16.f32 "
        "{%0,%1,%2,%3}, {%4,%5,%6,%7}, {%8,%9}, {%0,%1,%2,%3};"
        : "+f"(d[0]), "+f"(d[1]), "+f"(d[2]), "+f"(d[3])
        : "r"(a[0]), "r"(a[1]), "r"(a[2]), "r"(a[3]), "r"(b[0]), "r"(b[1]));
}
__device__ __forceinline__ void cp16(uint32_t dst, const void* src) {
    asm volatile("cp.async.cg.shared.global [%0], [%1], 16;"
                 :: "r"(dst), "l"(src) : "memory");
}
#define CP_COMMIT() asm volatile("cp.async.commit_group;" ::: "memory")
#define CP_WAIT(n)  asm volatile("cp.async.wait_group %0;" :: "n"(n) : "memory")

// ---------------- fused prep: nebs conversion + W2/W3 fp16 + out bias init ----------------
__global__ void prep_all_kernel(const unsigned int* __restrict__ raw,
                                const float* __restrict__ W2,
                                const float* __restrict__ W3,
                                const float* __restrict__ bfc,
                                float* __restrict__ out) {
    int p = blockIdx.x * 256 + threadIdx.x;
    if (p < N_VERTS * 7) {
        bool is64 = ((raw[1] | raw[3] | raw[5] | raw[7] | raw[9] | raw[11]) == 0u);
        int v;
        if (is64) v = (int)((const long long*)raw)[p];
        else      v = ((const int*)raw)[p];
        g_nebs[p] = v;
    }
    if (p < 28672) {
        int k = p >> 12, r = p & 4095, o = r >> 6, c = r & 63;
        g_W2h[p] = __float2half_rn(W2[(o * 64 + c) * 7 + k]);
    }
    if (p < 8192) {
        g_W3h[p] = __float2half_rn(W3[p]);
    }
    if (p < 512) {
        out[p] = bfc[p & 63];
    }
}

// ---------------- conv1: thread=(v, channel-quad), fp16 output ----------------
__global__ void __launch_bounds__(256) conv1_kernel(
    const float* __restrict__ x, const float* __restrict__ W1,
    const float* __restrict__ b1) {
    __shared__ float xs[64 * 16];   // [j=b*8+ci][v]
    const int tid = threadIdx.x;
    const int n0 = blockIdx.x * 16;
    const int v = tid >> 4, qq = tid & 15;   // channels qq*4..qq*4+3

    for (int p = tid; p < 1024; p += 256) {
        int j = p >> 4, t = p & 15, n = n0 + t;
        xs[p] = (n < N_VERTS) ? x[j * N_VERTS + n] : 0.f;
    }
    float wreg[4][8], bb[4];
#pragma unroll
    for (int j = 0; j < 4; j++) {
        float4 wa = *(const float4*)&W1[(qq * 4 + j) * 8];
        float4 wb = *(const float4*)&W1[(qq * 4 + j) * 8 + 4];
        wreg[j][0] = wa.x; wreg[j][1] = wa.y; wreg[j][2] = wa.z; wreg[j][3] = wa.w;
        wreg[j][4] = wb.x; wreg[j][5] = wb.y; wreg[j][6] = wb.z; wreg[j][7] = wb.w;
        bb[j] = b1[qq * 4 + j];
    }
    __syncthreads();

    const int n = n0 + v;
    if (n >= N_VERTS) return;
    uint2* dst = (uint2*)(g_h1 + (size_t)n * 512);

#pragma unroll
    for (int b = 0; b < 8; b++) {
        float xv[8];
#pragma unroll
        for (int ci = 0; ci < 8; ci++) xv[ci] = xs[(b * 8 + ci) * 16 + v];
        float acc[4];
#pragma unroll
        for (int j = 0; j < 4; j++) {
            float a = bb[j];
#pragma unroll
            for (int ci = 0; ci < 8; ci++) a = fmaf(wreg[j][ci], xv[ci], a);
            acc[j] = fmaxf(a, 0.f);
        }
        __half2 p0 = __floats2half2_rn(acc[0], acc[1]);
        __half2 p1 = __floats2half2_rn(acc[2], acc[3]);
        uint2 hv;
        hv.x = *reinterpret_cast<uint32_t*>(&p0);
        hv.y = *reinterpret_cast<uint32_t*>(&p1);
        dst[b * 16 + qq] = hv;
    }
}

// ---------------- conv2: mma.sync fp16 1-pass, M=128/block, 4 blocks/SM ----------------
#define C2_DSMEM (49152 + 256)

__device__ __forceinline__ void c2_issue(uint32_t base, const int* sidx,
                                         int k, int slot, int tid) {
    uint32_t wbase = base + (uint32_t)slot * 8192u;
    const char* wsh = (const char*)g_W2h + (size_t)k * 8192;
    for (int p = tid; p < 512; p += 256)
        cp16(wbase + swz((uint32_t)p * 16u), wsh + (size_t)p * 16);
    uint32_t abase = base + 16384u + (uint32_t)slot * 16384u;
    for (int p = tid; p < 1024; p += 256) {
        int r = p >> 3, c = p & 7;
        int nb = sidx[(r >> 3) * 7 + k];
        const char* src = (const char*)g_h1
                        + (size_t)nb * 1024 + (size_t)(r & 7) * 128
                        + (size_t)c * 16;
        cp16(abase + swz((uint32_t)(r * 128 + c * 16)), src);
    }
}

__global__ void __launch_bounds__(256, 4) conv2_mma_kernel(
    const float* __restrict__ b2) {
    extern __shared__ char dsm_raw[];
    __shared__ int sidx[112];
    __shared__ float b2s[64];
    const int tid = threadIdx.x, lane = tid & 31, wid = tid >> 5;
    const int n0 = blockIdx.x * 16;
    uint32_t raw = smem_u32(dsm_raw);
    uint32_t base = (raw + 127u) & ~127u;

    if (tid < 112) {
        int v = tid / 7, n = n0 + v;
        sidx[tid] = (n < N_VERTS) ? g_nebs[n * 7 + (tid - v * 7)] : 0;
    }
    if (tid < 64) b2s[tid] = b2[tid];
    __syncthreads();   // sidx ready

    c2_issue(base, sidx, 0, 0, tid);
    CP_COMMIT();

    float acc[2][4][4];
#pragma unroll
    for (int mt = 0; mt < 2; mt++)
#pragma unroll
        for (int nt = 0; nt < 4; nt++)
#pragma unroll
            for (int e = 0; e < 4; e++) acc[mt][nt][e] = 0.f;

    const int wm = wid >> 1, wn = wid & 1;    // 4 x 2 warps: M32 x N32 tiles
    const int m_base = wm * 32, n_base = wn * 32;

    for (int k = 0; k < 7; k++) {
        const int slot = k & 1;
        if (k < 6) { c2_issue(base, sidx, k + 1, slot ^ 1, tid); CP_COMMIT(); }
        if (k < 6) { CP_WAIT(1); } else { CP_WAIT(0); }
        __syncthreads();

        const uint32_t wbase = base + (uint32_t)slot * 8192u;
        const uint32_t abase = base + 16384u + (uint32_t)slot * 16384u;
#pragma unroll
        for (int kc = 0; kc < 4; kc++) {
            uint32_t Ah[2][4], Bh[2][4];
#pragma unroll
            for (int mt = 0; mt < 2; mt++) {
                int row = m_base + mt * 16 + (lane & 15);
                int ch = kc * 2 + (lane >> 4);
                uint32_t off = swz((uint32_t)(row * 128 + ch * 16));
                ldsm_x4(Ah[mt], abase + off);
            }
#pragma unroll
            for (int bt = 0; bt < 2; bt++) {
                int row = n_base + bt * 16 + (lane & 7) + ((lane >> 4) << 3);
                int ch = kc * 2 + ((lane >> 3) & 1);
                uint32_t off = swz((uint32_t)(row * 128 + ch * 16));
                ldsm_x4(Bh[bt], wbase + off);
            }
#pragma unroll
            for (int mt = 0; mt < 2; mt++)
#pragma unroll
                for (int nt = 0; nt < 4; nt++)
                    mma_f16(acc[mt][nt], Ah[mt], &Bh[nt >> 1][(nt & 1) * 2]);
        }
        __syncthreads();
    }

    // epilogue: bias + relu -> g_h2 [n][b][c] fp16
#pragma unroll
    for (int mt = 0; mt < 2; mt++) {
        int r0 = m_base + mt * 16 + (lane >> 2);
        int r1 = r0 + 8;
        int nA = n0 + (r0 >> 3), bA = r0 & 7;
        int nB = n0 + (r1 >> 3), bB = r1 & 7;
#pragma unroll
        for (int nt = 0; nt < 4; nt++) {
            int col = n_base + nt * 8 + (lane & 3) * 2;
            float bb0 = b2s[col], bb1 = b2s[col + 1];
            const float* a4 = acc[mt][nt];
            if (nA < N_VERTS) {
                __half2 r = __floats2half2_rn(fmaxf(a4[0] + bb0, 0.f),
                                              fmaxf(a4[1] + bb1, 0.f));
                *(__half2*)&g_h2[(size_t)nA * 512 + bA * 64 + col] = r;
            }
            if (nB < N_VERTS) {
                __half2 r = __floats2half2_rn(fmaxf(a4[2] + bb0, 0.f),
                                              fmaxf(a4[3] + bb1, 0.f));
                *(__half2*)&g_h2[(size_t)nB * 512 + bB * 64 + col] = r;
            }
        }
    }
}

// ---------------- pool + conv3: fused, fp16 1-pass, M=128 N=128 K=64 ----------------
// dsm: W3 [0,16K), A [16K,32K)
#define P3_DSMEM (32768 + 256)

__global__ void __launch_bounds__(256, 2) pool_conv3_mma_kernel(
    const float* __restrict__ b3) {
    extern __shared__ char dsm_raw[];
    __shared__ int sidx[112];
    const int tid = threadIdx.x, lane = tid & 31, wid = tid >> 5;
    const int n0 = blockIdx.x * 16;
    uint32_t raw = smem_u32(dsm_raw);
    uint32_t base = (raw + 127u) & ~127u;

    if (tid < 112) {
        int v = tid / 7, n = n0 + v;
        sidx[tid] = (n < N_POOL) ? g_nebs[n * 7 + (tid - v * 7)] : 0;
    }
    for (int p = tid; p < 1024; p += 256)
        cp16(base + swz((uint32_t)p * 16u), (const char*)g_W3h + (size_t)p * 16);
    CP_COMMIT();
    __syncthreads();

    // pool: max over 7 taps directly in fp16
    {
        int j = tid >> 1, hc = tid & 1;
        int v = j >> 3, b = j & 7;
        __half2 m[16];
        const __half2 NEG = __floats2half2_rn(-65504.f, -65504.f);
#pragma unroll
        for (int q = 0; q < 16; q++) m[q] = NEG;
        for (int k = 0; k < 7; k++) {
            const uint4* src = (const uint4*)
                &g_h2[(size_t)sidx[v * 7 + k] * 512 + b * 64 + hc * 32];
#pragma unroll
            for (int q = 0; q < 4; q++) {
                uint4 t = src[q];
                m[q * 4 + 0] = __hmax2(m[q * 4 + 0], *(__half2*)&t.x);
                m[q * 4 + 1] = __hmax2(m[q * 4 + 1], *(__half2*)&t.y);
                m[q * 4 + 2] = __hmax2(m[q * 4 + 2], *(__half2*)&t.z);
                m[q * 4 + 3] = __hmax2(m[q * 4 + 3], *(__half2*)&t.w);
            }
        }
        const uint32_t* mw = (const uint32_t*)m;
#pragma unroll
        for (int i = 0; i < 4; i++) {
            uint32_t off = swz((uint32_t)(j * 128 + hc * 64 + i * 16));
            *(uint4*)(dsm_raw + (base - raw) + 16384u + off) =
                make_uint4(mw[i * 4], mw[i * 4 + 1], mw[i * 4 + 2], mw[i * 4 + 3]);
        }
    }
    CP_WAIT(0);
    __syncthreads();

    const int wm = wid >> 1, wn = wid & 1;
    const int m_base = wm * 32, n_base = wn * 64;
    float acc[2][8][4];
#pragma unroll
    for (int mt = 0; mt < 2; mt++)
#pragma unroll
        for (int nt = 0; nt < 8; nt++)
#pragma unroll
            for (int e = 0; e < 4; e++) acc[mt][nt][e] = 0.f;

    const uint32_t abase = base + 16384u;
    const uint32_t bbase = base;
#pragma unroll
    for (int kc = 0; kc < 4; kc++) {
        uint32_t Ah[2][4], Bh[4][4];
#pragma unroll
        for (int mt = 0; mt < 2; mt++) {
            int row = m_base + mt * 16 + (lane & 15);
            int ch = kc * 2 + (lane >> 4);
            uint32_t off = swz((uint32_t)(row * 128 + ch * 16));
            ldsm_x4(Ah[mt], abase + off);
        }
#pragma unroll
        for (int bt = 0; bt < 4; bt++) {
            int row = n_base + bt * 16 + (lane & 7) + ((lane >> 4) << 3);
            int ch = kc * 2 + ((lane >> 3) & 1);
            uint32_t off = swz((uint32_t)(row * 128 + ch * 16));
            ldsm_x4(Bh[bt], bbase + off);
        }
#pragma unroll
        for (int mt = 0; mt < 2; mt++)
#pragma unroll
            for (int nt = 0; nt < 8; nt++)
                mma_f16(acc[mt][nt], Ah[mt], &Bh[nt >> 1][(nt & 1) * 2]);
    }

    // epilogue: bias + relu -> g_h3 [(o*N_POOL+n)*8+b]
#pragma unroll
    for (int mt = 0; mt < 2; mt++) {
        int r0 = m_base + mt * 16 + (lane >> 2);
        int r1 = r0 + 8;
        int v0 = r0 >> 3, b0i = r0 & 7;
        int v1 = r1 >> 3, b1i = r1 & 7;
#pragma unroll
        for (int nt = 0; nt < 8; nt++) {
            int col = n_base + nt * 8 + (lane & 3) * 2;
            float bb0 = __ldg(&b3[col]), bb1 = __ldg(&b3[col + 1]);
            const float* a4 = acc[mt][nt];
            if (n0 + v0 < N_POOL) {
                size_t idx = ((size_t)col * N_POOL + (n0 + v0)) * 8 + b0i;
                g_h3[idx] = fmaxf(a4[0] + bb0, 0.f);
                g_h3[idx + (size_t)N_POOL * 8] = fmaxf(a4[1] + bb1, 0.f);
            }
            if (n0 + v1 < N_POOL) {
                size_t idx = ((size_t)col * N_POOL + (n0 + v1)) * 8 + b1i;
                g_h3[idx] = fmaxf(a4[2] + bb0, 0.f);
                g_h3[idx + (size_t)N_POOL * 8] = fmaxf(a4[3] + bb1, 0.f);
            }
        }
    }
}

// ---------------- FC: 16 blocks.x, 4 channels each, low-reg ----------------
#define FC_NI (128 * N_POOL)   // 1310976

__global__ void __launch_bounds__(256) fc_kernel(
    const float* __restrict__ Wfc, float* __restrict__ out) {
    const int og = blockIdx.x;          // 16 groups of 4 channels
    const int nch = gridDim.y;
    const int chunk = blockIdx.y;
    const int i0 = (int)(((long long)FC_NI * chunk) / nch);
    const int i1 = (int)(((long long)FC_NI * (chunk + 1)) / nch);

    float acc[4][8];
#pragma unroll
    for (int j = 0; j < 4; j++)
#pragma unroll
        for (int b = 0; b < 8; b++) acc[j][b] = 0.f;

    // 4 i-elements per thread per iteration (float4 Wfc loads)
    for (int i = i0 + threadIdx.x * 4; i < i1; i += 1024) {
        float hv[4][8];
        const float4* hp = (const float4*)&g_h3[(size_t)i * 8];
#pragma unroll
        for (int q = 0; q < 8; q++) {
            float4 t = hp[q];
            hv[q >> 1][(q & 1) * 4 + 0] = t.x;
            hv[q >> 1][(q & 1) * 4 + 1] = t.y;
            hv[q >> 1][(q & 1) * 4 + 2] = t.z;
            hv[q >> 1][(q & 1) * 4 + 3] = t.w;
        }
#pragma unroll
        for (int j = 0; j < 4; j++) {
            float4 w = __ldcs((const float4*)&Wfc[(size_t)(og * 4 + j) * FC_NI + i]);
#pragma unroll
            for (int b = 0; b < 8; b++) {
                acc[j][b] = fmaf(w.x, hv[0][b], acc[j][b]);
                acc[j][b] = fmaf(w.y, hv[1][b], acc[j][b]);
                acc[j][b] = fmaf(w.z, hv[2][b], acc[j][b]);
                acc[j][b] = fmaf(w.w, hv[3][b], acc[j][b]);
            }
        }
    }

#pragma unroll
    for (int j = 0; j < 4; j++)
#pragma unroll
        for (int b = 0; b < 8; b++) {
            float v = acc[j][b];
#pragma unroll
            for (int s = 16; s > 0; s >>= 1)
                v += __shfl_xor_sync(0xffffffffu, v, s);
            acc[j][b] = v;
        }

    __shared__ float wred[8][32];
    const int lane = threadIdx.x & 31, warp = threadIdx.x >> 5;
    if (lane == 0) {
#pragma unroll
        for (int j = 0; j < 4; j++)
#pragma unroll
            for (int b = 0; b < 8; b++)
                wred[warp][j * 8 + b] = acc[j][b];
    }
    __syncthreads();
    if (threadIdx.x < 32) {
        int j = threadIdx.x >> 3, b = threadIdx.x & 7;
        float s = 0.f;
#pragma unroll
        for (int w = 0; w < 8; w++) s += wred[w][j * 8 + b];
        atomicAdd(&out[b * 64 + og * 4 + j], s);
    }
}

// ---------------- launch ----------------
extern "C" void kernel_launch(void* const* d_in, const int* in_sizes, int n_in,
                              void* d_out, int out_size) {
    const float* x    = (const float*)d_in[0];
    const void*  nebs = d_in[1];
    const float* W1   = (const float*)d_in[2];
    const float* b1   = (const float*)d_in[3];
    const float* W2   = (const float*)d_in[4];
    const float* b2   = (const float*)d_in[5];
    const float* W3   = (const float*)d_in[6];
    const float* b3   = (const float*)d_in[7];
    const float* Wfc  = (const float*)d_in[8];
    const float* bfc  = (const float*)d_in[9];
    float* out = (float*)d_out;

    cudaFuncSetAttribute(conv2_mma_kernel,
                         cudaFuncAttributeMaxDynamicSharedMemorySize, C2_DSMEM);
    cudaFuncSetAttribute(pool_conv3_mma_kernel,
                         cudaFuncAttributeMaxDynamicSharedMemorySize, P3_DSMEM);

    prep_all_kernel<<<(N_VERTS * 7 + 255) / 256, 256>>>(
        (const unsigned int*)nebs, W2, W3, bfc, out);
    conv1_kernel<<<(N_VERTS + 15) / 16, 256>>>(x, W1, b1);
    conv2_mma_kernel<<<(N_VERTS + 15) / 16, 256, C2_DSMEM>>>(b2);
    pool_conv3_mma_kernel<<<(N_POOL + 15) / 16, 256, P3_DSMEM>>>(b3);
    {
        dim3 grid(16, 96);
        fc_kernel<<<grid, 256>>>(Wfc, out);
    }
}

// round 16
// speedup vs baseline: 1.4166x; 1.4166x over previous
#include <cuda_runtime.h>
#include <cuda_fp16.h>
#include <cstdint>

#define N_VERTS 40962
#define N_POOL  10242

// h1 single fp16, layout [n][b][c] (c innermost, 512 halfs = 1KB per vertex)
__device__ __half g_h1[N_VERTS * 512];
__device__ __half g_h2[N_VERTS * 512];         // fp16 [n][b][c] (1KB per vertex)
__device__ __half g_h3[128 * N_POOL * 8];      // fp16 [(o*N_POOL+n)*8+b]
__device__ int   g_nebs[N_VERTS * 7];
__device__ __half g_W2h[7 * 64 * 64];          // [k][o][c] fp16
__device__ __half g_W3h[128 * 64];             // [o][c] fp16

// ---------------- helpers ----------------
__device__ __forceinline__ uint32_t smem_u32(const void* p) {
    uint32_t a;
    asm("{ .reg .u64 t; cvta.to.shared.u64 t, %1; cvt.u32.u64 %0, t; }"
        : "=r"(a) : "l"(p));
    return a;
}
__device__ __forceinline__ uint32_t swz(uint32_t off) {
    return off ^ ((off >> 3) & 0x70u);
}
__device__ __forceinline__ void ldsm_x4(uint32_t* r, uint32_t addr) {
    asm volatile(
        "ldmatrix.sync.aligned.m8n8.x4.shared.b16 {%0,%1,%2,%3}, [%4];"
        : "=r"(r[0]), "=r"(r[1]), "=r"(r[2]), "=r"(r[3]) : "r"(addr));
}
__device__ __forceinline__ void mma_f16(float* d, const uint32_t* a,
                                        const uint32_t* b) {
    asm volatile(
        "mma.sync.aligned.m16n8k16.row.col.f32.f16.f16.f32 "
        "{%0,%1,%2,%3}, {%4,%5,%6,%7}, {%8,%9}, {%0,%1,%2,%3};"
        : "+f"(d[0]), "+f"(d[1]), "+f"(d[2]), "+f"(d[3])
        : "r"(a[0]), "r"(a[1]), "r"(a[2]), "r"(a[3]), "r"(b[0]), "r"(b[1]));
}
__device__ __forceinline__ void cp16(uint32_t dst, const void* src) {
    asm volatile("cp.async.cg.shared.global [%0], [%1], 16;"
                 :: "r"(dst), "l"(src) : "memory");
}
#define CP_COMMIT() asm volatile("cp.async.commit_group;" ::: "memory")
#define CP_WAIT(n)  asm volatile("cp.async.wait_group %0;" :: "n"(n) : "memory")

// ---------------- fused prep: nebs conversion + W2/W3 fp16 + out bias init ----------------
__global__ void prep_all_kernel(const unsigned int* __restrict__ raw,
                                const float* __restrict__ W2,
                                const float* __restrict__ W3,
                                const float* __restrict__ bfc,
                                float* __restrict__ out) {
    int p = blockIdx.x * 256 + threadIdx.x;
    if (p < N_VERTS * 7) {
        bool is64 = ((raw[1] | raw[3] | raw[5] | raw[7] | raw[9] | raw[11]) == 0u);
        int v;
        if (is64) v = (int)((const long long*)raw)[p];
        else      v = ((const int*)raw)[p];
        g_nebs[p] = v;
    }
    if (p < 28672) {
        int k = p >> 12, r = p & 4095, o = r >> 6, c = r & 63;
        g_W2h[p] = __float2half_rn(W2[(o * 64 + c) * 7 + k]);
    }
    if (p < 8192) {
        g_W3h[p] = __float2half_rn(W3[p]);
    }
    if (p < 512) {
        out[p] = bfc[p & 63];
    }
}

// ---------------- conv1: thread=(v, channel-quad), fp16 output ----------------
__global__ void __launch_bounds__(256) conv1_kernel(
    const float* __restrict__ x, const float* __restrict__ W1,
    const float* __restrict__ b1) {
    __shared__ float xs[64 * 16];   // [j=b*8+ci][v]
    const int tid = threadIdx.x;
    const int n0 = blockIdx.x * 16;
    const int v = tid >> 4, qq = tid & 15;   // channels qq*4..qq*4+3

    for (int p = tid; p < 1024; p += 256) {
        int j = p >> 4, t = p & 15, n = n0 + t;
        xs[p] = (n < N_VERTS) ? x[j * N_VERTS + n] : 0.f;
    }
    float wreg[4][8], bb[4];
#pragma unroll
    for (int j = 0; j < 4; j++) {
        float4 wa = *(const float4*)&W1[(qq * 4 + j) * 8];
        float4 wb = *(const float4*)&W1[(qq * 4 + j) * 8 + 4];
        wreg[j][0] = wa.x; wreg[j][1] = wa.y; wreg[j][2] = wa.z; wreg[j][3] = wa.w;
        wreg[j][4] = wb.x; wreg[j][5] = wb.y; wreg[j][6] = wb.z; wreg[j][7] = wb.w;
        bb[j] = b1[qq * 4 + j];
    }
    __syncthreads();

    const int n = n0 + v;
    if (n >= N_VERTS) return;
    uint2* dst = (uint2*)(g_h1 + (size_t)n * 512);

#pragma unroll
    for (int b = 0; b < 8; b++) {
        float xv[8];
#pragma unroll
        for (int ci = 0; ci < 8; ci++) xv[ci] = xs[(b * 8 + ci) * 16 + v];
        float acc[4];
#pragma unroll
        for (int j = 0; j < 4; j++) {
            float a = bb[j];
#pragma unroll
            for (int ci = 0; ci < 8; ci++) a = fmaf(wreg[j][ci], xv[ci], a);
            acc[j] = fmaxf(a, 0.f);
        }
        __half2 p0 = __floats2half2_rn(acc[0], acc[1]);
        __half2 p1 = __floats2half2_rn(acc[2], acc[3]);
        uint2 hv;
        hv.x = *reinterpret_cast<uint32_t*>(&p0);
        hv.y = *reinterpret_cast<uint32_t*>(&p1);
        dst[b * 16 + qq] = hv;
    }
}

// ---------------- conv2: mma.sync fp16 1-pass, M=128/block, 4 blocks/SM ----------------
#define C2_DSMEM (49152 + 256)

__device__ __forceinline__ void c2_issue(uint32_t base, const int* sidx,
                                         int k, int slot, int tid) {
    uint32_t wbase = base + (uint32_t)slot * 8192u;
    const char* wsh = (const char*)g_W2h + (size_t)k * 8192;
    for (int p = tid; p < 512; p += 256)
        cp16(wbase + swz((uint32_t)p * 16u), wsh + (size_t)p * 16);
    uint32_t abase = base + 16384u + (uint32_t)slot * 16384u;
    for (int p = tid; p < 1024; p += 256) {
        int r = p >> 3, c = p & 7;
        int nb = sidx[(r >> 3) * 7 + k];
        const char* src = (const char*)g_h1
                        + (size_t)nb * 1024 + (size_t)(r & 7) * 128
                        + (size_t)c * 16;
        cp16(abase + swz((uint32_t)(r * 128 + c * 16)), src);
    }
}

__global__ void __launch_bounds__(256, 4) conv2_mma_kernel(
    const float* __restrict__ b2) {
    extern __shared__ char dsm_raw[];
    __shared__ int sidx[112];
    __shared__ float b2s[64];
    const int tid = threadIdx.x, lane = tid & 31, wid = tid >> 5;
    const int n0 = blockIdx.x * 16;
    uint32_t raw = smem_u32(dsm_raw);
    uint32_t base = (raw + 127u) & ~127u;

    if (tid < 112) {
        int v = tid / 7, n = n0 + v;
        sidx[tid] = (n < N_VERTS) ? g_nebs[n * 7 + (tid - v * 7)] : 0;
    }
    if (tid < 64) b2s[tid] = b2[tid];
    __syncthreads();   // sidx ready

    c2_issue(base, sidx, 0, 0, tid);
    CP_COMMIT();

    float acc[2][4][4];
#pragma unroll
    for (int mt = 0; mt < 2; mt++)
#pragma unroll
        for (int nt = 0; nt < 4; nt++)
#pragma unroll
            for (int e = 0; e < 4; e++) acc[mt][nt][e] = 0.f;

    const int wm = wid >> 1, wn = wid & 1;    // 4 x 2 warps: M32 x N32 tiles
    const int m_base = wm * 32, n_base = wn * 32;

    for (int k = 0; k < 7; k++) {
        const int slot = k & 1;
        if (k < 6) { c2_issue(base, sidx, k + 1, slot ^ 1, tid); CP_COMMIT(); }
        if (k < 6) { CP_WAIT(1); } else { CP_WAIT(0); }
        __syncthreads();

        const uint32_t wbase = base + (uint32_t)slot * 8192u;
        const uint32_t abase = base + 16384u + (uint32_t)slot * 16384u;
#pragma unroll
        for (int kc = 0; kc < 4; kc++) {
            uint32_t Ah[2][4], Bh[2][4];
#pragma unroll
            for (int mt = 0; mt < 2; mt++) {
                int row = m_base + mt * 16 + (lane & 15);
                int ch = kc * 2 + (lane >> 4);
                uint32_t off = swz((uint32_t)(row * 128 + ch * 16));
                ldsm_x4(Ah[mt], abase + off);
            }
#pragma unroll
            for (int bt = 0; bt < 2; bt++) {
                int row = n_base + bt * 16 + (lane & 7) + ((lane >> 4) << 3);
                int ch = kc * 2 + ((lane >> 3) & 1);
                uint32_t off = swz((uint32_t)(row * 128 + ch * 16));
                ldsm_x4(Bh[bt], wbase + off);
            }
#pragma unroll
            for (int mt = 0; mt < 2; mt++)
#pragma unroll
                for (int nt = 0; nt < 4; nt++)
                    mma_f16(acc[mt][nt], Ah[mt], &Bh[nt >> 1][(nt & 1) * 2]);
        }
        __syncthreads();
    }

    // epilogue: bias + relu -> g_h2 [n][b][c] fp16
#pragma unroll
    for (int mt = 0; mt < 2; mt++) {
        int r0 = m_base + mt * 16 + (lane >> 2);
        int r1 = r0 + 8;
        int nA = n0 + (r0 >> 3), bA = r0 & 7;
        int nB = n0 + (r1 >> 3), bB = r1 & 7;
#pragma unroll
        for (int nt = 0; nt < 4; nt++) {
            int col = n_base + nt * 8 + (lane & 3) * 2;
            float bb0 = b2s[col], bb1 = b2s[col + 1];
            const float* a4 = acc[mt][nt];
            if (nA < N_VERTS) {
                __half2 r = __floats2half2_rn(fmaxf(a4[0] + bb0, 0.f),
                                              fmaxf(a4[1] + bb1, 0.f));
                *(__half2*)&g_h2[(size_t)nA * 512 + bA * 64 + col] = r;
            }
            if (nB < N_VERTS) {
                __half2 r = __floats2half2_rn(fmaxf(a4[2] + bb0, 0.f),
                                              fmaxf(a4[3] + bb1, 0.f));
                *(__half2*)&g_h2[(size_t)nB * 512 + bB * 64 + col] = r;
            }
        }
    }
}

// ---------------- pool + conv3: fused, fp16 1-pass, M=128 N=128 K=64 ----------------
// dsm: W3 [0,16K), A [16K,32K)
#define P3_DSMEM (32768 + 256)

__global__ void __launch_bounds__(256, 2) pool_conv3_mma_kernel(
    const float* __restrict__ b3) {
    extern __shared__ char dsm_raw[];
    __shared__ int sidx[112];
    const int tid = threadIdx.x, lane = tid & 31, wid = tid >> 5;
    const int n0 = blockIdx.x * 16;
    uint32_t raw = smem_u32(dsm_raw);
    uint32_t base = (raw + 127u) & ~127u;

    if (tid < 112) {
        int v = tid / 7, n = n0 + v;
        sidx[tid] = (n < N_POOL) ? g_nebs[n * 7 + (tid - v * 7)] : 0;
    }
    for (int p = tid; p < 1024; p += 256)
        cp16(base + swz((uint32_t)p * 16u), (const char*)g_W3h + (size_t)p * 16);
    CP_COMMIT();
    __syncthreads();

    // pool: max over 7 taps directly in fp16
    {
        int j = tid >> 1, hc = tid & 1;
        int v = j >> 3, b = j & 7;
        __half2 m[16];
        const __half2 NEG = __floats2half2_rn(-65504.f, -65504.f);
#pragma unroll
        for (int q = 0; q < 16; q++) m[q] = NEG;
        for (int k = 0; k < 7; k++) {
            const uint4* src = (const uint4*)
                &g_h2[(size_t)sidx[v * 7 + k] * 512 + b * 64 + hc * 32];
#pragma unroll
            for (int q = 0; q < 4; q++) {
                uint4 t = src[q];
                m[q * 4 + 0] = __hmax2(m[q * 4 + 0], *(__half2*)&t.x);
                m[q * 4 + 1] = __hmax2(m[q * 4 + 1], *(__half2*)&t.y);
                m[q * 4 + 2] = __hmax2(m[q * 4 + 2], *(__half2*)&t.z);
                m[q * 4 + 3] = __hmax2(m[q * 4 + 3], *(__half2*)&t.w);
            }
        }
        const uint32_t* mw = (const uint32_t*)m;
#pragma unroll
        for (int i = 0; i < 4; i++) {
            uint32_t off = swz((uint32_t)(j * 128 + hc * 64 + i * 16));
            *(uint4*)(dsm_raw + (base - raw) + 16384u + off) =
                make_uint4(mw[i * 4], mw[i * 4 + 1], mw[i * 4 + 2], mw[i * 4 + 3]);
        }
    }
    CP_WAIT(0);
    __syncthreads();

    const int wm = wid >> 1, wn = wid & 1;
    const int m_base = wm * 32, n_base = wn * 64;
    float acc[2][8][4];
#pragma unroll
    for (int mt = 0; mt < 2; mt++)
#pragma unroll
        for (int nt = 0; nt < 8; nt++)
#pragma unroll
            for (int e = 0; e < 4; e++) acc[mt][nt][e] = 0.f;

    const uint32_t abase = base + 16384u;
    const uint32_t bbase = base;
#pragma unroll
    for (int kc = 0; kc < 4; kc++) {
        uint32_t Ah[2][4], Bh[4][4];
#pragma unroll
        for (int mt = 0; mt < 2; mt++) {
            int row = m_base + mt * 16 + (lane & 15);
            int ch = kc * 2 + (lane >> 4);
            uint32_t off = swz((uint32_t)(row * 128 + ch * 16));
            ldsm_x4(Ah[mt], abase + off);
        }
#pragma unroll
        for (int bt = 0; bt < 4; bt++) {
            int row = n_base + bt * 16 + (lane & 7) + ((lane >> 4) << 3);
            int ch = kc * 2 + ((lane >> 3) & 1);
            uint32_t off = swz((uint32_t)(row * 128 + ch * 16));
            ldsm_x4(Bh[bt], bbase + off);
        }
#pragma unroll
        for (int mt = 0; mt < 2; mt++)
#pragma unroll
            for (int nt = 0; nt < 8; nt++)
                mma_f16(acc[mt][nt], Ah[mt], &Bh[nt >> 1][(nt & 1) * 2]);
    }

    // epilogue: bias + relu -> g_h3 fp16 [(o*N_POOL+n)*8+b]
#pragma unroll
    for (int mt = 0; mt < 2; mt++) {
        int r0 = m_base + mt * 16 + (lane >> 2);
        int r1 = r0 + 8;
        int v0 = r0 >> 3, b0i = r0 & 7;
        int v1 = r1 >> 3, b1i = r1 & 7;
#pragma unroll
        for (int nt = 0; nt < 8; nt++) {
            int col = n_base + nt * 8 + (lane & 3) * 2;
            float bb0 = __ldg(&b3[col]), bb1 = __ldg(&b3[col + 1]);
            const float* a4 = acc[mt][nt];
            if (n0 + v0 < N_POOL) {
                size_t idx = ((size_t)col * N_POOL + (n0 + v0)) * 8 + b0i;
                g_h3[idx] = __float2half_rn(fmaxf(a4[0] + bb0, 0.f));
                g_h3[idx + (size_t)N_POOL * 8] =
                    __float2half_rn(fmaxf(a4[1] + bb1, 0.f));
            }
            if (n0 + v1 < N_POOL) {
                size_t idx = ((size_t)col * N_POOL + (n0 + v1)) * 8 + b1i;
                g_h3[idx] = __float2half_rn(fmaxf(a4[2] + bb0, 0.f));
                g_h3[idx + (size_t)N_POOL * 8] =
                    __float2half_rn(fmaxf(a4[3] + bb1, 0.f));
            }
        }
    }
}

// ---------------- FC: 8 blocks.x, 8 channels each ----------------
#define FC_NI (128 * N_POOL)   // 1310976

__global__ void __launch_bounds__(256) fc_kernel(
    const float* __restrict__ Wfc, float* __restrict__ out) {
    const int og = blockIdx.x;          // 8 groups of 8 channels
    const int nch = gridDim.y;
    const int chunk = blockIdx.y;
    const int i0 = (int)(((long long)FC_NI * chunk) / nch);
    const int i1 = (int)(((long long)FC_NI * (chunk + 1)) / nch);

    float acc[8][8];
#pragma unroll
    for (int j = 0; j < 8; j++)
#pragma unroll
        for (int b = 0; b < 8; b++) acc[j][b] = 0.f;

    // 4 i-elements per thread per iteration (float4 Wfc, uint4 h3-fp16)
    for (int i = i0 + threadIdx.x * 4; i < i1; i += 1024) {
        float hv[4][8];
        const uint4* hp = (const uint4*)&g_h3[(size_t)i * 8];
#pragma unroll
        for (int q = 0; q < 4; q++) {
            uint4 t = hp[q];
            float2 f0 = __half22float2(*(__half2*)&t.x);
            float2 f1 = __half22float2(*(__half2*)&t.y);
            float2 f2 = __half22float2(*(__half2*)&t.z);
            float2 f3 = __half22float2(*(__half2*)&t.w);
            hv[q][0] = f0.x; hv[q][1] = f0.y;
            hv[q][2] = f1.x; hv[q][3] = f1.y;
            hv[q][4] = f2.x; hv[q][5] = f2.y;
            hv[q][6] = f3.x; hv[q][7] = f3.y;
        }
#pragma unroll
        for (int j = 0; j < 8; j++) {
            float4 w = __ldcs((const float4*)&Wfc[(size_t)(og * 8 + j) * FC_NI + i]);
#pragma unroll
            for (int b = 0; b < 8; b++) {
                acc[j][b] = fmaf(w.x, hv[0][b], acc[j][b]);
                acc[j][b] = fmaf(w.y, hv[1][b], acc[j][b]);
                acc[j][b] = fmaf(w.z, hv[2][b], acc[j][b]);
                acc[j][b] = fmaf(w.w, hv[3][b], acc[j][b]);
            }
        }
    }

#pragma unroll
    for (int j = 0; j < 8; j++)
#pragma unroll
        for (int b = 0; b < 8; b++) {
            float v = acc[j][b];
#pragma unroll
            for (int s = 16; s > 0; s >>= 1)
                v += __shfl_xor_sync(0xffffffffu, v, s);
            acc[j][b] = v;
        }

    __shared__ float wred[8][64];
    const int lane = threadIdx.x & 31, warp = threadIdx.x >> 5;
    if (lane == 0) {
#pragma unroll
        for (int j = 0; j < 8; j++)
#pragma unroll
            for (int b = 0; b < 8; b++)
                wred[warp][j * 8 + b] = acc[j][b];
    }
    __syncthreads();
    if (threadIdx.x < 64) {
        int j = threadIdx.x >> 3, b = threadIdx.x & 7;
        float s = 0.f;
#pragma unroll
        for (int w = 0; w < 8; w++) s += wred[w][j * 8 + b];
        atomicAdd(&out[b * 64 + og * 8 + j], s);
    }
}

// ---------------- launch ----------------
extern "C" void kernel_launch(void* const* d_in, const int* in_sizes, int n_in,
                              void* d_out, int out_size) {
    const float* x    = (const float*)d_in[0];
    const void*  nebs = d_in[1];
    const float* W1   = (const float*)d_in[2];
    const float* b1   = (const float*)d_in[3];
    const float* W2   = (const float*)d_in[4];
    const float* b2   = (const float*)d_in[5];
    const float* W3   = (const float*)d_in[6];
    const float* b3   = (const float*)d_in[7];
    const float* Wfc  = (const float*)d_in[8];
    const float* bfc  = (const float*)d_in[9];
    float* out = (float*)d_out;

    cudaFuncSetAttribute(conv2_mma_kernel,
                         cudaFuncAttributeMaxDynamicSharedMemorySize, C2_DSMEM);
    cudaFuncSetAttribute(pool_conv3_mma_kernel,
                         cudaFuncAttributeMaxDynamicSharedMemorySize, P3_DSMEM);

    prep_all_kernel<<<(N_VERTS * 7 + 255) / 256, 256>>>(
        (const unsigned int*)nebs, W2, W3, bfc, out);
    conv1_kernel<<<(N_VERTS + 15) / 16, 256>>>(x, W1, b1);
    conv2_mma_kernel<<<(N_VERTS + 15) / 16, 256, C2_DSMEM>>>(b2);
    pool_conv3_mma_kernel<<<(N_POOL + 15) / 16, 256, P3_DSMEM>>>(b3);
    {
        dim3 grid(8, 96);
        fc_kernel<<<grid, 256>>>(Wfc, out);
    }
}